// round 13
// baseline (speedup 1.0000x reference)
#include <cuda_runtime.h>
#include <cuda_fp16.h>
#include <math.h>
#include <stdint.h>

#define BATCH  4
#define SEQ    4096
#define DMODEL 1024
#define DFF    4096
#define KSEL   1024
#define MROWS  4096

// ------------------------- device scratch (no allocs) -------------------------
__device__ float g_scores[BATCH * SEQ];
__device__ int   g_selidx[MROWS];
__device__ float g_gate[MROWS];
__device__ int   g_flag[BATCH * SEQ];            // 1 if row selected
__device__ __half g_A[(size_t)MROWS * DMODEL];   // gathered tokens, fp16
__device__ __half g_H[(size_t)MROWS * DFF];      // GELU(h), fp16
__device__ __half g_W1[(size_t)DFF * DMODEL];    // W1^T  [N][K]
__device__ __half g_W2[(size_t)DMODEL * DFF];    // W2^T  [N][K]

// ------------------------------ helpers ------------------------------
__device__ __forceinline__ uint32_t smem_u32(const void* p) {
    uint32_t a;
    asm("{ .reg .u64 t; cvta.to.shared.u64 t, %1; cvt.u32.u64 %0, t; }"
        : "=r"(a) : "l"(p));
    return a;
}

__device__ __forceinline__ void ldsm4(uint32_t* r, uint32_t addr) {
    asm volatile("ldmatrix.sync.aligned.m8n8.x4.shared.b16 {%0,%1,%2,%3}, [%4];"
                 : "=r"(r[0]), "=r"(r[1]), "=r"(r[2]), "=r"(r[3]) : "r"(addr));
}

__device__ __forceinline__ void mma16816(float* c, const uint32_t* a, const uint32_t* b) {
    asm volatile(
        "mma.sync.aligned.m16n8k16.row.col.f32.f16.f16.f32 "
        "{%0,%1,%2,%3}, {%4,%5,%6,%7}, {%8,%9}, {%0,%1,%2,%3};"
        : "+f"(c[0]), "+f"(c[1]), "+f"(c[2]), "+f"(c[3])
        : "r"(a[0]), "r"(a[1]), "r"(a[2]), "r"(a[3]), "r"(b[0]), "r"(b[1]));
}

__device__ __forceinline__ void cp16(uint32_t dst, const void* src) {
    asm volatile("cp.async.cg.shared.global [%0], [%1], 16;" :: "r"(dst), "l"(src));
}

// SW128 swizzle: 128B rows, 8 x 16B slots, slot XOR row&7
__device__ __forceinline__ uint32_t swz128(int row, int u) {
    return (uint32_t)(row * 128 + ((u ^ (row & 7)) << 4));
}

// ------------------------------ router (+flag clear) ------------------------------
__global__ void router_kernel(const float* __restrict__ x,
                              const float* __restrict__ rw,
                              const float* __restrict__ rb) {
    int gtid = blockIdx.x * blockDim.x + threadIdx.x;
    if (gtid < BATCH * SEQ) g_flag[gtid] = 0;
    int warp = gtid >> 5;
    int lane = threadIdx.x & 31;
    if (warp >= BATCH * SEQ) return;
    const float4* xr = (const float4*)(x + (size_t)warp * DMODEL);
    const float4* w4 = (const float4*)rw;
    float acc = 0.f;
#pragma unroll 4
    for (int i = lane; i < DMODEL / 4; i += 32) {
        float4 a = xr[i], w = w4[i];
        acc += a.x * w.x + a.y * w.y + a.z * w.z + a.w * w.w;
    }
#pragma unroll
    for (int o = 16; o; o >>= 1) acc += __shfl_xor_sync(0xffffffffu, acc, o);
    if (lane == 0) g_scores[warp] = acc + rb[0];
}

// ----- top-k via 4-level radix select, warp-shuffle suffix scan -----
__global__ void topk_select() {
    __shared__ uint32_t skey[SEQ];
    __shared__ int hist[256];
    __shared__ int sK;
    __shared__ uint32_t spfx;
    __shared__ int cntG, cntE;
    const int b = blockIdx.x, tid = threadIdx.x, T = blockDim.x;  // T = 1024

    for (int i = tid; i < SEQ; i += T) {
        uint32_t u = __float_as_uint(g_scores[b * SEQ + i]);
        skey[i] = (u & 0x80000000u) ? ~u : (u | 0x80000000u);
    }
    if (tid == 0) { sK = KSEL; spfx = 0; cntG = 0; cntE = 0; }
    if (tid < 256) hist[tid] = 0;
    __syncthreads();

    for (int level = 0; level < 4; ++level) {
        const int shift = 24 - level * 8;
        uint32_t pfx = spfx;
        const int k = sK;
        for (int i = tid; i < SEQ; i += T) {
            uint32_t u = skey[i];
            if (level == 0 || (u >> (shift + 8)) == pfx)
                atomicAdd(&hist[(u >> shift) & 0xFF], 1);
        }
        __syncthreads();
        // warp 0: suffix scan over 256 bins (8 bins per lane, contiguous)
        if (tid < 32) {
            int h[8], s[8];
#pragma unroll
            for (int j = 0; j < 8; ++j) h[j] = hist[tid * 8 + j];
            s[7] = h[7];
#pragma unroll
            for (int j = 6; j >= 0; --j) s[j] = h[j] + s[j + 1];
            int laneSum = s[0];
            int x = laneSum;
#pragma unroll
            for (int off = 1; off < 32; off <<= 1) {
                int t = __shfl_down_sync(0xffffffffu, x, off);
                if (tid + off < 32) x += t;
            }
            int exclHi = x - laneSum;   // sum over lanes > tid
#pragma unroll
            for (int j = 0; j < 8; ++j) {
                int suf = s[j] + exclHi;                            // count >= bin
                int sufN = (j < 7) ? s[j + 1] + exclHi : exclHi;    // count > bin
                if (suf >= k && sufN < k) {
                    spfx = (pfx << 8) | (uint32_t)(tid * 8 + j);
                    sK = k - sufN;
                }
            }
        }
        __syncthreads();
        if (tid < 256) hist[tid] = 0;
        __syncthreads();
    }
    const uint32_t thr = spfx;
    const int kE = sK;
    const int G = KSEL - kE;
    for (int i = tid; i < SEQ; i += T) {
        uint32_t u = skey[i];
        int slot = -1;
        if (u > thr) slot = atomicAdd(&cntG, 1);
        else if (u == thr) {
            int e = atomicAdd(&cntE, 1);
            if (e < kE) slot = G + e;
        }
        if (slot >= 0) {
            g_selidx[b * KSEL + slot] = i;
            g_flag[b * SEQ + i] = 1;
            float s = g_scores[b * SEQ + i];
            g_gate[b * KSEL + slot] = 1.f / (1.f + expf(-s));
        }
    }
}

// -------------------- gather selected rows -> fp16 --------------------
__global__ void gather_convert(const float* __restrict__ x) {
    int r = blockIdx.x;
    int b = r >> 10;
    int pos = g_selidx[r];
    const float4* src = (const float4*)(x + ((size_t)b * SEQ + pos) * DMODEL);
    float4 v = src[threadIdx.x];
    __align__(8) __half h[4];
    h[0] = __float2half(v.x); h[1] = __float2half(v.y);
    h[2] = __float2half(v.z); h[3] = __float2half(v.w);
    size_t o = (size_t)r * DMODEL + 4 * threadIdx.x;
    *(uint2*)&g_A[o] = *(uint2*)h;
}

// ------------- transpose weights -> fp16 [N][K], half2 stores -------------
template<int W>
__global__ void transpose_w(const float* __restrict__ src) {
    constexpr int R = (W == 0) ? DMODEL : DFF;    // K of the GEMM
    constexpr int C = (W == 0) ? DFF : DMODEL;    // N of the GEMM
    __half* O = (W == 0) ? g_W1 : g_W2;
    __shared__ float t[32][33];                   // t[r][c]
    int c0 = blockIdx.x * 32, r0 = blockIdx.y * 32;
    int tx = threadIdx.x, ty = threadIdx.y;       // (32, 8)
#pragma unroll
    for (int j = 0; j < 32; j += 8)
        t[ty + j][tx] = src[(size_t)(r0 + ty + j) * C + c0 + tx];
    __syncthreads();
    int tid = ty * 32 + tx;
    int cc = tid >> 4;              // 0..15
    int rr = (tid & 15) * 2;        // 0,2,...,30
#pragma unroll
    for (int h = 0; h < 2; ++h) {
        int c = cc + h * 16;
        __half2 v = __floats2half2_rn(t[rr][c], t[rr + 1][c]);
        *(__half2*)&O[(size_t)(c0 + c) * R + r0 + rr] = v;
    }
}

// ------------------------ zero output (skip selected rows) ------------------------
__global__ void zero_kernel(float4* __restrict__ out) {
    int row = blockIdx.x;
    if (g_flag[row]) return;
    out[(size_t)row * 256 + threadIdx.x] = make_float4(0.f, 0.f, 0.f, 0.f);
}

// ------------- HMMA GEMM: CTA MTx128, warp (MT/2)x32, K-chunk 64 -------------
// MT=128: R7-proven geometry. MT=64: finer tiles for wave balance (GEMM1).
#define STAGES 3

template<int KDIM, int MT, int EPI>
__global__ __launch_bounds__(256, 2)
void hmma_gemm(const float* __restrict__ bias, float* __restrict__ out) {
    extern __shared__ __align__(128) char smem[];
    constexpr int MTC = MT / 32;                     // A fragments per warp
    constexpr int STAGE_BYTES = (MT + 128) * 128;
    const int tid = threadIdx.x, l = tid & 31, wid = tid >> 5;
    const int wm = wid >> 2, wn = wid & 3;
    const int bm = blockIdx.y * MT, bn = blockIdx.x * 128;
    const uint32_t sb = smem_u32(smem);
    constexpr int NC = KDIM / 64;

    const __half *A, *B;
    if (EPI == 0) { A = g_A; B = g_W1; }
    else          { A = g_H; B = g_W2; }

    float acc[MTC][4][4];
#pragma unroll
    for (int i = 0; i < MTC; ++i)
#pragma unroll
        for (int j = 0; j < 4; ++j)
#pragma unroll
            for (int k = 0; k < 4; ++k) acc[i][j][k] = 0.f;

    auto load_stage = [&](int ck, int slot) {
        uint32_t sbase = sb + slot * STAGE_BYTES;
#pragma unroll
        for (int j = 0; j < MT / 32; ++j) {          // A: MT rows x 128B
            int w = tid + j * 256;
            int row = w >> 3, u = w & 7;
            cp16(sbase + swz128(row, u),
                 A + (size_t)(bm + row) * KDIM + ck * 64 + u * 8);
        }
#pragma unroll
        for (int j = 0; j < 4; ++j) {                // B: 128 rows x 128B
            int w = tid + j * 256;
            int row = w >> 3, u = w & 7;
            cp16(sbase + MT * 128 + swz128(row, u),
                 B + (size_t)(bn + row) * KDIM + ck * 64 + u * 8);
        }
        asm volatile("cp.async.commit_group;" ::: "memory");
    };

    load_stage(0, 0);
    load_stage(1, 1);

    for (int c = 0; c < NC; ++c) {
        asm volatile("cp.async.wait_group 1;" ::: "memory");
        __syncthreads();
        if (c + 2 < NC) load_stage(c + 2, (c + 2) % STAGES);
        uint32_t sbase = sb + (c % STAGES) * STAGE_BYTES;
#pragma unroll
        for (int s = 0; s < 4; ++s) {
            uint32_t ah[MTC][4], bh[4][2];
#pragma unroll
            for (int mt = 0; mt < MTC; ++mt) {
                int row = wm * (MT / 2) + mt * 16 + (l & 15);
                int u = s * 2 + (l >> 4);
                ldsm4(ah[mt], sbase + swz128(row, u));
            }
#pragma unroll
            for (int p = 0; p < 2; ++p) {
                int row = wn * 32 + p * 16 + ((l >> 4) << 3) + (l & 7);
                int u = s * 2 + ((l >> 3) & 1);
                uint32_t rh[4];
                ldsm4(rh, sbase + MT * 128 + swz128(row, u));
                bh[p * 2][0] = rh[0]; bh[p * 2][1] = rh[1];
                bh[p * 2 + 1][0] = rh[2]; bh[p * 2 + 1][1] = rh[3];
            }
#pragma unroll
            for (int mt = 0; mt < MTC; ++mt)
#pragma unroll
                for (int nt = 0; nt < 4; ++nt)
                    mma16816(acc[mt][nt], ah[mt], bh[nt]);
        }
    }

    // ------------------------- epilogue -------------------------
    const int r0base = bm + wm * (MT / 2);
    const int c0base = bn + wn * 32;
#pragma unroll
    for (int mt = 0; mt < MTC; ++mt) {
#pragma unroll
        for (int half = 0; half < 2; ++half) {
            int row = r0base + mt * 16 + (l >> 2) + half * 8;
            if (EPI == 0) {
#pragma unroll
                for (int nt = 0; nt < 4; ++nt) {
                    int col = c0base + nt * 8 + (l & 3) * 2;
                    float v0 = acc[mt][nt][half * 2 + 0] + __ldg(&bias[col]);
                    float v1 = acc[mt][nt][half * 2 + 1] + __ldg(&bias[col + 1]);
                    v0 = 0.5f * v0 * (1.f + erff(v0 * 0.70710678118654752f));
                    v1 = 0.5f * v1 * (1.f + erff(v1 * 0.70710678118654752f));
                    *(__half2*)&g_H[(size_t)row * DFF + col] = __floats2half2_rn(v0, v1);
                }
            } else {
                int b = row >> 10;
                int pos = g_selidx[row];
                float gt = g_gate[row];
                size_t o = ((size_t)b * SEQ + pos) * DMODEL;
#pragma unroll
                for (int nt = 0; nt < 4; ++nt) {
                    int col = c0base + nt * 8 + (l & 3) * 2;
                    float2 w;
                    w.x = (acc[mt][nt][half * 2 + 0] + __ldg(&bias[col])) * gt;
                    w.y = (acc[mt][nt][half * 2 + 1] + __ldg(&bias[col + 1])) * gt;
                    *(float2*)&out[o + col] = w;
                }
            }
        }
    }
}

#define GEMM1_SMEM (STAGES * (64 + 128) * 128)
#define GEMM2_SMEM (STAGES * (128 + 128) * 128)

// ------------------------------ launch ------------------------------
extern "C" void kernel_launch(void* const* d_in, const int* in_sizes, int n_in,
                              void* d_out, int out_size) {
    const float* x  = (const float*)d_in[0];
    const float* rw = (const float*)d_in[1];
    const float* rb = (const float*)d_in[2];
    const float* w1 = (const float*)d_in[3];
    const float* b1 = (const float*)d_in[4];
    const float* w2 = (const float*)d_in[5];
    const float* b2 = (const float*)d_in[6];
    float* out = (float*)d_out;

    // One-time host-side setup (first call is the non-captured correctness run).
    static cudaStream_t s1 = nullptr, s2 = nullptr;
    static cudaEvent_t e0 = nullptr, eT = nullptr, eK = nullptr, eZ = nullptr;
    if (!s1) {
        cudaStreamCreateWithFlags(&s1, cudaStreamNonBlocking);
        cudaStreamCreateWithFlags(&s2, cudaStreamNonBlocking);
        cudaEventCreateWithFlags(&e0, cudaEventDisableTiming);
        cudaEventCreateWithFlags(&eT, cudaEventDisableTiming);
        cudaEventCreateWithFlags(&eK, cudaEventDisableTiming);
        cudaEventCreateWithFlags(&eZ, cudaEventDisableTiming);
        cudaFuncSetAttribute(hmma_gemm<DMODEL, 64, 0>,
                             cudaFuncAttributeMaxDynamicSharedMemorySize, GEMM1_SMEM);
        cudaFuncSetAttribute(hmma_gemm<DFF, 128, 1>,
                             cudaFuncAttributeMaxDynamicSharedMemorySize, GEMM2_SMEM);
    }

    // Fork s1: weight transposes (independent of everything else)
    cudaEventRecord(e0, 0);
    cudaStreamWaitEvent(s1, e0, 0);
    transpose_w<0><<<dim3(DFF / 32, DMODEL / 32), dim3(32, 8), 0, s1>>>(w1);
    transpose_w<1><<<dim3(DMODEL / 32, DFF / 32), dim3(32, 8), 0, s1>>>(w2);
    cudaEventRecord(eT, s1);

    // Main chain: router -> topk -> gather
    router_kernel<<<(BATCH * SEQ) / 8, 256>>>(x, rw, rb);
    topk_select<<<BATCH, 1024>>>();

    // Fork s2: zero output (depends only on topk), overlaps gather + GEMM1
    cudaEventRecord(eK, 0);
    cudaStreamWaitEvent(s2, eK, 0);
    zero_kernel<<<BATCH * SEQ, 256, 0, s2>>>((float4*)out);
    cudaEventRecord(eZ, s2);

    gather_convert<<<MROWS, 256>>>(x);

    // Join transposes, run GEMM1 (+GELU -> H), 64-row M tiles for wave balance
    cudaStreamWaitEvent(0, eT, 0);
    hmma_gemm<DMODEL, 64, 0><<<dim3(DFF / 128, MROWS / 64), 256, GEMM1_SMEM>>>(b1, nullptr);

    // Join zero, run GEMM2 (+gate+scatter), proven 128x128 tiles
    cudaStreamWaitEvent(0, eZ, 0);
    hmma_gemm<DFF, 128, 1><<<dim3(DMODEL / 128, MROWS / 128), 256, GEMM2_SMEM>>>(b2, out);
}

// round 15
// speedup vs baseline: 1.0494x; 1.0494x over previous
#include <cuda_runtime.h>
#include <cuda_fp16.h>
#include <math.h>
#include <stdint.h>

#define BATCH  4
#define SEQ    4096
#define DMODEL 1024
#define DFF    4096
#define KSEL   1024
#define MROWS  4096

// ------------------------- device scratch (no allocs) -------------------------
__device__ float g_scores[BATCH * SEQ];
__device__ int   g_selidx[MROWS];
__device__ float g_gate[MROWS];
__device__ int   g_flag[BATCH * SEQ];            // 1 if row selected
__device__ __half g_A[(size_t)MROWS * DMODEL];   // gathered tokens, fp16
__device__ __half g_H[(size_t)MROWS * DFF];      // GELU(h), fp16
__device__ __half g_W1[(size_t)DFF * DMODEL];    // W1^T  [N][K]
__device__ __half g_W2[(size_t)DMODEL * DFF];    // W2^T  [N][K]

// ------------------------------ helpers ------------------------------
__device__ __forceinline__ uint32_t smem_u32(const void* p) {
    uint32_t a;
    asm("{ .reg .u64 t; cvta.to.shared.u64 t, %1; cvt.u32.u64 %0, t; }"
        : "=r"(a) : "l"(p));
    return a;
}

__device__ __forceinline__ void ldsm4(uint32_t* r, uint32_t addr) {
    asm volatile("ldmatrix.sync.aligned.m8n8.x4.shared.b16 {%0,%1,%2,%3}, [%4];"
                 : "=r"(r[0]), "=r"(r[1]), "=r"(r[2]), "=r"(r[3]) : "r"(addr));
}

__device__ __forceinline__ void mma16816(float* c, const uint32_t* a, const uint32_t* b) {
    asm volatile(
        "mma.sync.aligned.m16n8k16.row.col.f32.f16.f16.f32 "
        "{%0,%1,%2,%3}, {%4,%5,%6,%7}, {%8,%9}, {%0,%1,%2,%3};"
        : "+f"(c[0]), "+f"(c[1]), "+f"(c[2]), "+f"(c[3])
        : "r"(a[0]), "r"(a[1]), "r"(a[2]), "r"(a[3]), "r"(b[0]), "r"(b[1]));
}

__device__ __forceinline__ void cp16(uint32_t dst, const void* src) {
    asm volatile("cp.async.cg.shared.global [%0], [%1], 16;" :: "r"(dst), "l"(src));
}

// SW128 swizzle: 128B rows, 8 x 16B slots, slot XOR row&7
__device__ __forceinline__ uint32_t swz128(int row, int u) {
    return (uint32_t)(row * 128 + ((u ^ (row & 7)) << 4));
}

// ------------------------------ router (+flag clear) ------------------------------
__global__ void router_kernel(const float* __restrict__ x,
                              const float* __restrict__ rw,
                              const float* __restrict__ rb) {
    int gtid = blockIdx.x * blockDim.x + threadIdx.x;
    if (gtid < BATCH * SEQ) g_flag[gtid] = 0;
    int warp = gtid >> 5;
    int lane = threadIdx.x & 31;
    if (warp >= BATCH * SEQ) return;
    const float4* xr = (const float4*)(x + (size_t)warp * DMODEL);
    const float4* w4 = (const float4*)rw;
    float acc = 0.f;
#pragma unroll 4
    for (int i = lane; i < DMODEL / 4; i += 32) {
        float4 a = xr[i], w = w4[i];
        acc += a.x * w.x + a.y * w.y + a.z * w.z + a.w * w.w;
    }
#pragma unroll
    for (int o = 16; o; o >>= 1) acc += __shfl_xor_sync(0xffffffffu, acc, o);
    if (lane == 0) g_scores[warp] = acc + rb[0];
}

// ----- top-k via 4-level radix select, warp-shuffle suffix scan -----
__global__ void topk_select() {
    __shared__ uint32_t skey[SEQ];
    __shared__ int hist[256];
    __shared__ int sK;
    __shared__ uint32_t spfx;
    __shared__ int cntG, cntE;
    const int b = blockIdx.x, tid = threadIdx.x, T = blockDim.x;  // T = 1024

    for (int i = tid; i < SEQ; i += T) {
        uint32_t u = __float_as_uint(g_scores[b * SEQ + i]);
        skey[i] = (u & 0x80000000u) ? ~u : (u | 0x80000000u);
    }
    if (tid == 0) { sK = KSEL; spfx = 0; cntG = 0; cntE = 0; }
    if (tid < 256) hist[tid] = 0;
    __syncthreads();

    for (int level = 0; level < 4; ++level) {
        const int shift = 24 - level * 8;
        uint32_t pfx = spfx;
        const int k = sK;
        for (int i = tid; i < SEQ; i += T) {
            uint32_t u = skey[i];
            if (level == 0 || (u >> (shift + 8)) == pfx)
                atomicAdd(&hist[(u >> shift) & 0xFF], 1);
        }
        __syncthreads();
        // warp 0: suffix scan over 256 bins (8 bins per lane, contiguous)
        if (tid < 32) {
            int h[8], s[8];
#pragma unroll
            for (int j = 0; j < 8; ++j) h[j] = hist[tid * 8 + j];
            s[7] = h[7];
#pragma unroll
            for (int j = 6; j >= 0; --j) s[j] = h[j] + s[j + 1];
            int laneSum = s[0];
            int x = laneSum;
#pragma unroll
            for (int off = 1; off < 32; off <<= 1) {
                int t = __shfl_down_sync(0xffffffffu, x, off);
                if (tid + off < 32) x += t;
            }
            int exclHi = x - laneSum;   // sum over lanes > tid
#pragma unroll
            for (int j = 0; j < 8; ++j) {
                int suf = s[j] + exclHi;                            // count >= bin
                int sufN = (j < 7) ? s[j + 1] + exclHi : exclHi;    // count > bin
                if (suf >= k && sufN < k) {
                    spfx = (pfx << 8) | (uint32_t)(tid * 8 + j);
                    sK = k - sufN;
                }
            }
        }
        __syncthreads();
        if (tid < 256) hist[tid] = 0;
        __syncthreads();
    }
    const uint32_t thr = spfx;
    const int kE = sK;
    const int G = KSEL - kE;
    for (int i = tid; i < SEQ; i += T) {
        uint32_t u = skey[i];
        int slot = -1;
        if (u > thr) slot = atomicAdd(&cntG, 1);
        else if (u == thr) {
            int e = atomicAdd(&cntE, 1);
            if (e < kE) slot = G + e;
        }
        if (slot >= 0) {
            g_selidx[b * KSEL + slot] = i;
            g_flag[b * SEQ + i] = 1;
            float s = g_scores[b * SEQ + i];
            g_gate[b * KSEL + slot] = 1.f / (1.f + expf(-s));
        }
    }
}

// -------------------- gather selected rows -> fp16 --------------------
__global__ void gather_convert(const float* __restrict__ x) {
    int r = blockIdx.x;
    int b = r >> 10;
    int pos = g_selidx[r];
    const float4* src = (const float4*)(x + ((size_t)b * SEQ + pos) * DMODEL);
    float4 v = src[threadIdx.x];
    __align__(8) __half h[4];
    h[0] = __float2half(v.x); h[1] = __float2half(v.y);
    h[2] = __float2half(v.z); h[3] = __float2half(v.w);
    size_t o = (size_t)r * DMODEL + 4 * threadIdx.x;
    *(uint2*)&g_A[o] = *(uint2*)h;
}

// ------------- transpose weights -> fp16 [N][K], half2 stores -------------
template<int W>
__global__ void transpose_w(const float* __restrict__ src) {
    constexpr int R = (W == 0) ? DMODEL : DFF;    // K of the GEMM
    constexpr int C = (W == 0) ? DFF : DMODEL;    // N of the GEMM
    __half* O = (W == 0) ? g_W1 : g_W2;
    __shared__ float t[32][33];                   // t[r][c]
    int c0 = blockIdx.x * 32, r0 = blockIdx.y * 32;
    int tx = threadIdx.x, ty = threadIdx.y;       // (32, 8)
#pragma unroll
    for (int j = 0; j < 32; j += 8)
        t[ty + j][tx] = src[(size_t)(r0 + ty + j) * C + c0 + tx];
    __syncthreads();
    int tid = ty * 32 + tx;
    int cc = tid >> 4;              // 0..15
    int rr = (tid & 15) * 2;        // 0,2,...,30
#pragma unroll
    for (int h = 0; h < 2; ++h) {
        int c = cc + h * 16;
        __half2 v = __floats2half2_rn(t[rr][c], t[rr + 1][c]);
        *(__half2*)&O[(size_t)(c0 + c) * R + r0 + rr] = v;
    }
}

// ------------------------ zero output (skip selected rows) ------------------------
__global__ void zero_kernel(float4* __restrict__ out) {
    int row = blockIdx.x;
    if (g_flag[row]) return;
    out[(size_t)row * 256 + threadIdx.x] = make_float4(0.f, 0.f, 0.f, 0.f);
}

// ------------- HMMA GEMM: CTA 128x128, warp 64x32, K-chunk 64 (proven) -------------
#define STAGES 3
#define STAGE_BYTES 32768
#define GEMM_SMEM (STAGES * STAGE_BYTES)

template<int KDIM, int EPI>
__global__ __launch_bounds__(256, 2)
void hmma_gemm(const float* __restrict__ bias, float* __restrict__ out) {
    extern __shared__ __align__(128) char smem[];
    const int tid = threadIdx.x, l = tid & 31, wid = tid >> 5;
    const int wm = wid >> 2, wn = wid & 3;
    const int bm = blockIdx.y * 128, bn = blockIdx.x * 128;
    const uint32_t sb = smem_u32(smem);
    constexpr int NC = KDIM / 64;

    const __half *A, *B;
    if (EPI == 0) { A = g_A; B = g_W1; }
    else          { A = g_H; B = g_W2; }

    float acc[4][4][4];
#pragma unroll
    for (int i = 0; i < 4; ++i)
#pragma unroll
        for (int j = 0; j < 4; ++j)
#pragma unroll
            for (int k = 0; k < 4; ++k) acc[i][j][k] = 0.f;

    auto load_stage = [&](int ck, int slot) {
        uint32_t sbase = sb + slot * STAGE_BYTES;
#pragma unroll
        for (int j = 0; j < 4; ++j) {
            int w = tid + j * 256;
            int row = w >> 3, u = w & 7;
            cp16(sbase + swz128(row, u),
                 A + (size_t)(bm + row) * KDIM + ck * 64 + u * 8);
        }
#pragma unroll
        for (int j = 0; j < 4; ++j) {
            int w = tid + j * 256;
            int row = w >> 3, u = w & 7;
            cp16(sbase + 16384 + swz128(row, u),
                 B + (size_t)(bn + row) * KDIM + ck * 64 + u * 8);
        }
        asm volatile("cp.async.commit_group;" ::: "memory");
    };

    load_stage(0, 0);
    load_stage(1, 1);

    for (int c = 0; c < NC; ++c) {
        asm volatile("cp.async.wait_group 1;" ::: "memory");
        __syncthreads();
        if (c + 2 < NC) load_stage(c + 2, (c + 2) % STAGES);
        uint32_t sbase = sb + (c % STAGES) * STAGE_BYTES;
#pragma unroll
        for (int s = 0; s < 4; ++s) {
            uint32_t ah[4][4], bh[4][2];
#pragma unroll
            for (int mt = 0; mt < 4; ++mt) {
                int row = wm * 64 + mt * 16 + (l & 15);
                int u = s * 2 + (l >> 4);
                ldsm4(ah[mt], sbase + swz128(row, u));
            }
#pragma unroll
            for (int p = 0; p < 2; ++p) {
                int row = wn * 32 + p * 16 + ((l >> 4) << 3) + (l & 7);
                int u = s * 2 + ((l >> 3) & 1);
                uint32_t rh[4];
                ldsm4(rh, sbase + 16384 + swz128(row, u));
                bh[p * 2][0] = rh[0]; bh[p * 2][1] = rh[1];
                bh[p * 2 + 1][0] = rh[2]; bh[p * 2 + 1][1] = rh[3];
            }
#pragma unroll
            for (int mt = 0; mt < 4; ++mt)
#pragma unroll
                for (int nt = 0; nt < 4; ++nt)
                    mma16816(acc[mt][nt], ah[mt], bh[nt]);
        }
    }

    // ------------------------- epilogue -------------------------
    const int r0base = bm + wm * 64;
    const int c0base = bn + wn * 32;
#pragma unroll
    for (int mt = 0; mt < 4; ++mt) {
#pragma unroll
        for (int half = 0; half < 2; ++half) {
            int row = r0base + mt * 16 + (l >> 2) + half * 8;
            if (EPI == 0) {
#pragma unroll
                for (int nt = 0; nt < 4; ++nt) {
                    int col = c0base + nt * 8 + (l & 3) * 2;
                    float v0 = acc[mt][nt][half * 2 + 0] + __ldg(&bias[col]);
                    float v1 = acc[mt][nt][half * 2 + 1] + __ldg(&bias[col + 1]);
                    v0 = 0.5f * v0 * (1.f + erff(v0 * 0.70710678118654752f));
                    v1 = 0.5f * v1 * (1.f + erff(v1 * 0.70710678118654752f));
                    *(__half2*)&g_H[(size_t)row * DFF + col] = __floats2half2_rn(v0, v1);
                }
            } else {
                int b = row >> 10;
                int pos = g_selidx[row];
                float gt = g_gate[row];
                size_t o = ((size_t)b * SEQ + pos) * DMODEL;
#pragma unroll
                for (int nt = 0; nt < 4; ++nt) {
                    int col = c0base + nt * 8 + (l & 3) * 2;
                    float2 w;
                    w.x = (acc[mt][nt][half * 2 + 0] + __ldg(&bias[col])) * gt;
                    w.y = (acc[mt][nt][half * 2 + 1] + __ldg(&bias[col + 1])) * gt;
                    *(float2*)&out[o + col] = w;
                }
            }
        }
    }
}

// ------------------------------ launch ------------------------------
extern "C" void kernel_launch(void* const* d_in, const int* in_sizes, int n_in,
                              void* d_out, int out_size) {
    const float* x  = (const float*)d_in[0];
    const float* rw = (const float*)d_in[1];
    const float* rb = (const float*)d_in[2];
    const float* w1 = (const float*)d_in[3];
    const float* b1 = (const float*)d_in[4];
    const float* w2 = (const float*)d_in[5];
    const float* b2 = (const float*)d_in[6];
    float* out = (float*)d_out;

    // One-time host-side setup (first call is the non-captured correctness run).
    static cudaStream_t s1 = nullptr, s2 = nullptr;
    static cudaEvent_t e0 = nullptr, eT = nullptr, eK = nullptr, eZ = nullptr;
    if (!s1) {
        cudaStreamCreateWithFlags(&s1, cudaStreamNonBlocking);
        cudaStreamCreateWithFlags(&s2, cudaStreamNonBlocking);
        cudaEventCreateWithFlags(&e0, cudaEventDisableTiming);
        cudaEventCreateWithFlags(&eT, cudaEventDisableTiming);
        cudaEventCreateWithFlags(&eK, cudaEventDisableTiming);
        cudaEventCreateWithFlags(&eZ, cudaEventDisableTiming);
        cudaFuncSetAttribute(hmma_gemm<DMODEL, 0>,
                             cudaFuncAttributeMaxDynamicSharedMemorySize, GEMM_SMEM);
        cudaFuncSetAttribute(hmma_gemm<DFF, 1>,
                             cudaFuncAttributeMaxDynamicSharedMemorySize, GEMM_SMEM);
    }

    // Fork s1: weight transposes (independent of everything else)
    cudaEventRecord(e0, 0);
    cudaStreamWaitEvent(s1, e0, 0);
    transpose_w<0><<<dim3(DFF / 32, DMODEL / 32), dim3(32, 8), 0, s1>>>(w1);
    transpose_w<1><<<dim3(DMODEL / 32, DFF / 32), dim3(32, 8), 0, s1>>>(w2);
    cudaEventRecord(eT, s1);

    // Main chain: router -> topk -> gather
    router_kernel<<<(BATCH * SEQ) / 8, 256>>>(x, rw, rb);
    topk_select<<<BATCH, 1024>>>();

    // Fork s2: zero output (depends only on topk), overlaps gather + GEMM1
    cudaEventRecord(eK, 0);
    cudaStreamWaitEvent(s2, eK, 0);
    zero_kernel<<<BATCH * SEQ, 256, 0, s2>>>((float4*)out);
    cudaEventRecord(eZ, s2);

    gather_convert<<<MROWS, 256>>>(x);

    // Join transposes, run GEMM1 (+GELU -> H)
    cudaStreamWaitEvent(0, eT, 0);
    hmma_gemm<DMODEL, 0><<<dim3(DFF / 128, MROWS / 128), 256, GEMM_SMEM>>>(b1, nullptr);

    // Join zero, run GEMM2 (+gate+scatter)
    cudaStreamWaitEvent(0, eZ, 0);
    hmma_gemm<DFF, 1><<<dim3(DMODEL / 128, MROWS / 128), 256, GEMM_SMEM>>>(b2, out);
}

// round 17
// speedup vs baseline: 1.0850x; 1.0339x over previous
#include <cuda_runtime.h>
#include <cuda_fp16.h>
#include <math.h>
#include <stdint.h>

#define BATCH  4
#define SEQ    4096
#define DMODEL 1024
#define DFF    4096
#define KSEL   1024
#define MROWS  4096

#define NTILE1 1024     // GEMM1: 32 m-blocks x 32 n-blocks
#define NTILE2 256      // GEMM2: 32 m-blocks x 8 n-blocks
#define NCTA   296      // 148 SMs x 2 CTAs

// ------------------------- device scratch (no allocs) -------------------------
__device__ float g_scores[BATCH * SEQ];
__device__ int   g_selidx[MROWS];
__device__ float g_gate[MROWS];
__device__ int   g_flag[BATCH * SEQ];
__device__ int   g_work;
__device__ int   g_ready[32];
__device__ __half g_A[(size_t)MROWS * DMODEL];
__device__ __half g_H[(size_t)MROWS * DFF];
__device__ __half g_W1[(size_t)DFF * DMODEL];    // W1^T [N][K]
__device__ __half g_W2[(size_t)DMODEL * DFF];    // W2^T [N][K]

// ------------------------------ helpers ------------------------------
__device__ __forceinline__ uint32_t smem_u32(const void* p) {
    uint32_t a;
    asm("{ .reg .u64 t; cvta.to.shared.u64 t, %1; cvt.u32.u64 %0, t; }"
        : "=r"(a) : "l"(p));
    return a;
}

__device__ __forceinline__ void ldsm4(uint32_t* r, uint32_t addr) {
    asm volatile("ldmatrix.sync.aligned.m8n8.x4.shared.b16 {%0,%1,%2,%3}, [%4];"
                 : "=r"(r[0]), "=r"(r[1]), "=r"(r[2]), "=r"(r[3]) : "r"(addr));
}

__device__ __forceinline__ void mma16816(float* c, const uint32_t* a, const uint32_t* b) {
    asm volatile(
        "mma.sync.aligned.m16n8k16.row.col.f32.f16.f16.f32 "
        "{%0,%1,%2,%3}, {%4,%5,%6,%7}, {%8,%9}, {%0,%1,%2,%3};"
        : "+f"(c[0]), "+f"(c[1]), "+f"(c[2]), "+f"(c[3])
        : "r"(a[0]), "r"(a[1]), "r"(a[2]), "r"(a[3]), "r"(b[0]), "r"(b[1]));
}

__device__ __forceinline__ void cp16(uint32_t dst, const void* src) {
    asm volatile("cp.async.cg.shared.global [%0], [%1], 16;" :: "r"(dst), "l"(src));
}

__device__ __forceinline__ uint32_t swz128(int row, int u) {
    return (uint32_t)(row * 128 + ((u ^ (row & 7)) << 4));
}

// ------------------------------ router (+state reset) ------------------------------
__global__ void router_kernel(const float* __restrict__ x,
                              const float* __restrict__ rw,
                              const float* __restrict__ rb) {
    int gtid = blockIdx.x * blockDim.x + threadIdx.x;
    if (gtid < BATCH * SEQ) g_flag[gtid] = 0;
    if (gtid == 0) g_work = 0;
    if (gtid < 32) g_ready[gtid] = 0;
    int warp = gtid >> 5;
    int lane = threadIdx.x & 31;
    if (warp >= BATCH * SEQ) return;
    const float4* xr = (const float4*)(x + (size_t)warp * DMODEL);
    const float4* w4 = (const float4*)rw;
    float acc = 0.f;
#pragma unroll 4
    for (int i = lane; i < DMODEL / 4; i += 32) {
        float4 a = xr[i], w = w4[i];
        acc += a.x * w.x + a.y * w.y + a.z * w.z + a.w * w.w;
    }
#pragma unroll
    for (int o = 16; o; o >>= 1) acc += __shfl_xor_sync(0xffffffffu, acc, o);
    if (lane == 0) g_scores[warp] = acc + rb[0];
}

// ----- top-k via 4-level radix select, warp-shuffle suffix scan -----
__global__ void topk_select() {
    __shared__ uint32_t skey[SEQ];
    __shared__ int hist[256];
    __shared__ int sK;
    __shared__ uint32_t spfx;
    __shared__ int cntG, cntE;
    const int b = blockIdx.x, tid = threadIdx.x, T = blockDim.x;

    for (int i = tid; i < SEQ; i += T) {
        uint32_t u = __float_as_uint(g_scores[b * SEQ + i]);
        skey[i] = (u & 0x80000000u) ? ~u : (u | 0x80000000u);
    }
    if (tid == 0) { sK = KSEL; spfx = 0; cntG = 0; cntE = 0; }
    if (tid < 256) hist[tid] = 0;
    __syncthreads();

    for (int level = 0; level < 4; ++level) {
        const int shift = 24 - level * 8;
        uint32_t pfx = spfx;
        const int k = sK;
        for (int i = tid; i < SEQ; i += T) {
            uint32_t u = skey[i];
            if (level == 0 || (u >> (shift + 8)) == pfx)
                atomicAdd(&hist[(u >> shift) & 0xFF], 1);
        }
        __syncthreads();
        if (tid < 32) {
            int h[8], s[8];
#pragma unroll
            for (int j = 0; j < 8; ++j) h[j] = hist[tid * 8 + j];
            s[7] = h[7];
#pragma unroll
            for (int j = 6; j >= 0; --j) s[j] = h[j] + s[j + 1];
            int laneSum = s[0];
            int x = laneSum;
#pragma unroll
            for (int off = 1; off < 32; off <<= 1) {
                int t = __shfl_down_sync(0xffffffffu, x, off);
                if (tid + off < 32) x += t;
            }
            int exclHi = x - laneSum;
#pragma unroll
            for (int j = 0; j < 8; ++j) {
                int suf = s[j] + exclHi;
                int sufN = (j < 7) ? s[j + 1] + exclHi : exclHi;
                if (suf >= k && sufN < k) {
                    spfx = (pfx << 8) | (uint32_t)(tid * 8 + j);
                    sK = k - sufN;
                }
            }
        }
        __syncthreads();
        if (tid < 256) hist[tid] = 0;
        __syncthreads();
    }
    const uint32_t thr = spfx;
    const int kE = sK;
    const int G = KSEL - kE;
    for (int i = tid; i < SEQ; i += T) {
        uint32_t u = skey[i];
        int slot = -1;
        if (u > thr) slot = atomicAdd(&cntG, 1);
        else if (u == thr) {
            int e = atomicAdd(&cntE, 1);
            if (e < kE) slot = G + e;
        }
        if (slot >= 0) {
            g_selidx[b * KSEL + slot] = i;
            g_flag[b * SEQ + i] = 1;
            float s = g_scores[b * SEQ + i];
            g_gate[b * KSEL + slot] = 1.f / (1.f + expf(-s));
        }
    }
}

// -------------------- gather selected rows -> fp16 --------------------
__global__ void gather_convert(const float* __restrict__ x) {
    int r = blockIdx.x;
    int b = r >> 10;
    int pos = g_selidx[r];
    const float4* src = (const float4*)(x + ((size_t)b * SEQ + pos) * DMODEL);
    float4 v = src[threadIdx.x];
    __align__(8) __half h[4];
    h[0] = __float2half(v.x); h[1] = __float2half(v.y);
    h[2] = __float2half(v.z); h[3] = __float2half(v.w);
    size_t o = (size_t)r * DMODEL + 4 * threadIdx.x;
    *(uint2*)&g_A[o] = *(uint2*)h;
}

// ------------- transpose weights -> fp16 [N][K], half2 stores -------------
template<int W>
__global__ void transpose_w(const float* __restrict__ src) {
    constexpr int R = (W == 0) ? DMODEL : DFF;
    constexpr int C = (W == 0) ? DFF : DMODEL;
    __half* O = (W == 0) ? g_W1 : g_W2;
    __shared__ float t[32][33];
    int c0 = blockIdx.x * 32, r0 = blockIdx.y * 32;
    int tx = threadIdx.x, ty = threadIdx.y;
#pragma unroll
    for (int j = 0; j < 32; j += 8)
        t[ty + j][tx] = src[(size_t)(r0 + ty + j) * C + c0 + tx];
    __syncthreads();
    int tid = ty * 32 + tx;
    int cc = tid >> 4;
    int rr = (tid & 15) * 2;
#pragma unroll
    for (int h = 0; h < 2; ++h) {
        int c = cc + h * 16;
        __half2 v = __floats2half2_rn(t[rr][c], t[rr + 1][c]);
        *(__half2*)&O[(size_t)(c0 + c) * R + r0 + rr] = v;
    }
}

// ------------------------ zero output (skip selected rows) ------------------------
__global__ void zero_kernel(float4* __restrict__ out) {
    int row = blockIdx.x;
    if (g_flag[row]) return;
    out[(size_t)row * 256 + threadIdx.x] = make_float4(0.f, 0.f, 0.f, 0.f);
}

// ------------- GEMM tile routine: 128x128, warp 64x32, K-chunk 64 (proven) -------------
#define STAGES 3
#define STAGE_BYTES 32768
#define GEMM_SMEM (STAGES * STAGE_BYTES)

template<int KDIM, int EPI>
__device__ __forceinline__ void gemm_tile(const __half* __restrict__ A,
                                          const __half* __restrict__ B,
                                          const float* __restrict__ bias,
                                          float* __restrict__ out,
                                          int bm, int bn, uint32_t sb) {
    const int tid = threadIdx.x, l = tid & 31, wid = tid >> 5;
    const int wm = wid >> 2, wn = wid & 3;
    constexpr int NC = KDIM / 64;

    float acc[4][4][4];
#pragma unroll
    for (int i = 0; i < 4; ++i)
#pragma unroll
        for (int j = 0; j < 4; ++j)
#pragma unroll
            for (int k = 0; k < 4; ++k) acc[i][j][k] = 0.f;

    auto load_stage = [&](int ck, int slot) {
        uint32_t sbase = sb + slot * STAGE_BYTES;
#pragma unroll
        for (int j = 0; j < 4; ++j) {
            int w = tid + j * 256;
            int row = w >> 3, u = w & 7;
            cp16(sbase + swz128(row, u),
                 A + (size_t)(bm + row) * KDIM + ck * 64 + u * 8);
        }
#pragma unroll
        for (int j = 0; j < 4; ++j) {
            int w = tid + j * 256;
            int row = w >> 3, u = w & 7;
            cp16(sbase + 16384 + swz128(row, u),
                 B + (size_t)(bn + row) * KDIM + ck * 64 + u * 8);
        }
        asm volatile("cp.async.commit_group;" ::: "memory");
    };

    load_stage(0, 0);
    load_stage(1, 1);

    for (int c = 0; c < NC; ++c) {
        if (c < NC - 1)
            asm volatile("cp.async.wait_group 1;" ::: "memory");
        else
            asm volatile("cp.async.wait_group 0;" ::: "memory");
        __syncthreads();
        if (c + 2 < NC) load_stage(c + 2, (c + 2) % STAGES);
        uint32_t sbase = sb + (c % STAGES) * STAGE_BYTES;
#pragma unroll
        for (int s = 0; s < 4; ++s) {
            uint32_t ah[4][4], bh[4][2];
#pragma unroll
            for (int mt = 0; mt < 4; ++mt) {
                int row = wm * 64 + mt * 16 + (l & 15);
                int u = s * 2 + (l >> 4);
                ldsm4(ah[mt], sbase + swz128(row, u));
            }
#pragma unroll
            for (int p = 0; p < 2; ++p) {
                int row = wn * 32 + p * 16 + ((l >> 4) << 3) + (l & 7);
                int u = s * 2 + ((l >> 3) & 1);
                uint32_t rh[4];
                ldsm4(rh, sbase + 16384 + swz128(row, u));
                bh[p * 2][0] = rh[0]; bh[p * 2][1] = rh[1];
                bh[p * 2 + 1][0] = rh[2]; bh[p * 2 + 1][1] = rh[3];
            }
#pragma unroll
            for (int mt = 0; mt < 4; ++mt)
#pragma unroll
                for (int nt = 0; nt < 4; ++nt)
                    mma16816(acc[mt][nt], ah[mt], bh[nt]);
        }
    }

    const int r0base = bm + wm * 64;
    const int c0base = bn + wn * 32;
#pragma unroll
    for (int mt = 0; mt < 4; ++mt) {
#pragma unroll
        for (int half = 0; half < 2; ++half) {
            int row = r0base + mt * 16 + (l >> 2) + half * 8;
            if (EPI == 0) {
#pragma unroll
                for (int nt = 0; nt < 4; ++nt) {
                    int col = c0base + nt * 8 + (l & 3) * 2;
                    float v0 = acc[mt][nt][half * 2 + 0] + __ldg(&bias[col]);
                    float v1 = acc[mt][nt][half * 2 + 1] + __ldg(&bias[col + 1]);
                    v0 = 0.5f * v0 * (1.f + erff(v0 * 0.70710678118654752f));
                    v1 = 0.5f * v1 * (1.f + erff(v1 * 0.70710678118654752f));
                    *(__half2*)&g_H[(size_t)row * DFF + col] = __floats2half2_rn(v0, v1);
                }
            } else {
                int b = row >> 10;
                int pos = g_selidx[row];
                float gt = g_gate[row];
                size_t o = ((size_t)b * SEQ + pos) * DMODEL;
#pragma unroll
                for (int nt = 0; nt < 4; ++nt) {
                    int col = c0base + nt * 8 + (l & 3) * 2;
                    float2 w;
                    w.x = (acc[mt][nt][half * 2 + 0] + __ldg(&bias[col])) * gt;
                    w.y = (acc[mt][nt][half * 2 + 1] + __ldg(&bias[col + 1])) * gt;
                    *(float2*)&out[o + col] = w;
                }
            }
        }
    }
}

// --------- persistent fused GEMM1+GEMM2 with dynamic tile queue ---------
__global__ __launch_bounds__(256, 2)
void fused_gemms(const float* __restrict__ b1, const float* __restrict__ b2,
                 float* __restrict__ out) {
    extern __shared__ __align__(128) char smem[];
    const uint32_t sb = smem_u32(smem);
    __shared__ int s_tile;
    const int tid = threadIdx.x;

    for (;;) {
        if (tid == 0) s_tile = atomicAdd(&g_work, 1);
        __syncthreads();
        int t = s_tile;
        if (t >= NTILE1 + NTILE2) return;

        if (t < NTILE1) {
            int m = t >> 5, n = t & 31;            // m-major: early row-blocks finish first
            gemm_tile<DMODEL, 0>(g_A, g_W1, b1, nullptr, m * 128, n * 128, sb);
            __threadfence();
            __syncthreads();
            if (tid == 0) atomicAdd(&g_ready[m], 1);
        } else {
            int t2 = t - NTILE1;
            int m = t2 >> 3, n = t2 & 7;
            if (tid == 0) {
                while (atomicAdd(&g_ready[m], 0) < 32) __nanosleep(100);
                __threadfence();
            }
            __syncthreads();
            gemm_tile<DFF, 1>(g_H, g_W2, b2, out, m * 128, n * 128, sb);
        }
        __syncthreads();   // SMEM reuse guard before next tile
    }
}

// ------------------------------ launch ------------------------------
extern "C" void kernel_launch(void* const* d_in, const int* in_sizes, int n_in,
                              void* d_out, int out_size) {
    const float* x  = (const float*)d_in[0];
    const float* rw = (const float*)d_in[1];
    const float* rb = (const float*)d_in[2];
    const float* w1 = (const float*)d_in[3];
    const float* b1 = (const float*)d_in[4];
    const float* w2 = (const float*)d_in[5];
    const float* b2 = (const float*)d_in[6];
    float* out = (float*)d_out;

    static cudaStream_t s1 = nullptr, s2 = nullptr;
    static cudaEvent_t e0 = nullptr, eT = nullptr, eK = nullptr, eZ = nullptr;
    if (!s1) {
        cudaStreamCreateWithFlags(&s1, cudaStreamNonBlocking);
        cudaStreamCreateWithFlags(&s2, cudaStreamNonBlocking);
        cudaEventCreateWithFlags(&e0, cudaEventDisableTiming);
        cudaEventCreateWithFlags(&eT, cudaEventDisableTiming);
        cudaEventCreateWithFlags(&eK, cudaEventDisableTiming);
        cudaEventCreateWithFlags(&eZ, cudaEventDisableTiming);
        cudaFuncSetAttribute(fused_gemms,
                             cudaFuncAttributeMaxDynamicSharedMemorySize, GEMM_SMEM);
    }

    // Fork s1: weight transposes (independent)
    cudaEventRecord(e0, 0);
    cudaStreamWaitEvent(s1, e0, 0);
    transpose_w<0><<<dim3(DFF / 32, DMODEL / 32), dim3(32, 8), 0, s1>>>(w1);
    transpose_w<1><<<dim3(DMODEL / 32, DFF / 32), dim3(32, 8), 0, s1>>>(w2);
    cudaEventRecord(eT, s1);

    // Main chain: router (+counter reset) -> topk -> gather
    router_kernel<<<(BATCH * SEQ) / 8, 256>>>(x, rw, rb);
    topk_select<<<BATCH, 1024>>>();

    // Fork s2: zero output (rows disjoint from GEMM2 scatter -> full overlap)
    cudaEventRecord(eK, 0);
    cudaStreamWaitEvent(s2, eK, 0);
    zero_kernel<<<BATCH * SEQ, 256, 0, s2>>>((float4*)out);
    cudaEventRecord(eZ, s2);

    gather_convert<<<MROWS, 256>>>(x);

    // Join transposes, run fused persistent GEMM1+GEMM2
    cudaStreamWaitEvent(0, eT, 0);
    fused_gemms<<<NCTA, 256, GEMM_SMEM>>>(b1, b2, out);

    // Join zero at the end (capture requires all forks rejoin)
    cudaStreamWaitEvent(0, eZ, 0);
}